// round 15
// baseline (speedup 1.0000x reference)
#include <cuda_runtime.h>
#include <cuda_bf16.h>
#include <math.h>
#include <stdint.h>

#define NHEADS   4
#define WIN      7
#define NTOK     49
#define CDIM     128
#define NWIN     64
#define NBLK     2048
#define NTHREADS 256

// ---------------- mma.sync helpers ----------------
__device__ __forceinline__ uint32_t smem_u32(const void* p) {
    uint32_t a;
    asm("{ .reg .u64 t; cvta.to.shared.u64 t, %1; cvt.u32.u64 %0, t; }" : "=r"(a) : "l"(p));
    return a;
}
__device__ __forceinline__ void ldmx4(uint32_t* d, uint32_t addr) {
    asm volatile("ldmatrix.sync.aligned.m8n8.x4.shared.b16 {%0,%1,%2,%3}, [%4];"
        : "=r"(d[0]), "=r"(d[1]), "=r"(d[2]), "=r"(d[3]) : "r"(addr));
}
__device__ __forceinline__ void ldmx4t(uint32_t* d, uint32_t addr) {
    asm volatile("ldmatrix.sync.aligned.m8n8.x4.trans.shared.b16 {%0,%1,%2,%3}, [%4];"
        : "=r"(d[0]), "=r"(d[1]), "=r"(d[2]), "=r"(d[3]) : "r"(addr));
}
__device__ __forceinline__ void mma16816(float* c, const uint32_t* a, uint32_t b0, uint32_t b1) {
    asm volatile("mma.sync.aligned.m16n8k16.row.col.f32.bf16.bf16.f32 "
        "{%0,%1,%2,%3}, {%4,%5,%6,%7}, {%8,%9}, {%0,%1,%2,%3};"
        : "+f"(c[0]), "+f"(c[1]), "+f"(c[2]), "+f"(c[3])
        : "r"(a[0]), "r"(a[1]), "r"(a[2]), "r"(a[3]), "r"(b0), "r"(b1));
}
__device__ __forceinline__ void split2(float x0, float x1, uint32_t &hp, uint32_t &lp) {
    __nv_bfloat16 h0 = __float2bfloat16(x0);
    __nv_bfloat16 h1 = __float2bfloat16(x1);
    __nv_bfloat16 l0 = __float2bfloat16(x0 - __bfloat162float(h0));
    __nv_bfloat16 l1 = __float2bfloat16(x1 - __bfloat162float(h1));
    hp = ((uint32_t)__bfloat16_as_ushort(h1) << 16) | __bfloat16_as_ushort(h0);
    lp = ((uint32_t)__bfloat16_as_ushort(l1) << 16) | __bfloat16_as_ushort(l0);
}

// ---------------- smem regions (bytes); XOR-swizzled 256B rows ----------------
#define RA_HI   0
#define RA_LO   12544
#define RK_HI   25088
#define RK_LO   39424
#define RV_HI   53760
#define RV_LO   70144
#define SMEM_TOTAL_B 86528
#define AP_HI   RA_HI
#define AP_LO   RA_LO

// ---------------- device globals ----------------
__device__ float g_comb2[NWIN * NHEADS * NTOK * 64];   // padded to 64 cols
__device__ uint4 g_BqkvF[12288];
__device__ uint4 g_BprojF[4096];

__device__ __forceinline__ uint32_t pack_split(float w0, float w1, int img) {
    __nv_bfloat16 h0 = __float2bfloat16(w0);
    __nv_bfloat16 h1 = __float2bfloat16(w1);
    if (img == 0)
        return ((uint32_t)__bfloat16_as_ushort(h1) << 16) | __bfloat16_as_ushort(h0);
    __nv_bfloat16 l0 = __float2bfloat16(w0 - __bfloat162float(h0));
    __nv_bfloat16 l1 = __float2bfloat16(w1 - __bfloat162float(h1));
    return ((uint32_t)__bfloat16_as_ushort(l1) << 16) | __bfloat16_as_ushort(l0);
}

#define COMB_BLKS 2401
__global__ void swin_prol_kernel(const float* __restrict__ rel_table,
                                 const float* __restrict__ mask,
                                 const float* __restrict__ qkv_w,
                                 const float* __restrict__ proj_w) {
    if (blockIdx.x < COMB_BLKS) {
        int e = blockIdx.x * blockDim.x + threadIdx.x;
        if (e >= NWIN * NHEADS * NTOK * NTOK) return;
        int j = e % NTOK;
        int t = e / NTOK;
        int i = t % NTOK;  t /= NTOK;
        int h = t % NHEADS;
        int w = t / NHEADS;
        int yi = i / WIN, xi = i % WIN, yj = j / WIN, xj = j % WIN;
        int r = (yi - yj + WIN - 1) * (2 * WIN - 1) + (xi - xj + WIN - 1);
        g_comb2[(((w * NHEADS + h) * NTOK) + i) * 64 + j] =
            rel_table[r * NHEADS + h] + mask[(w * NTOK + i) * NTOK + j];
    } else {
        int e = (blockIdx.x - COMB_BLKS) * blockDim.x + threadIdx.x;
        if (e >= 16384) return;
        bool isproj = (e >= 12288);
        int idx = isproj ? (e - 12288) : e;
        int lane = idx & 31;
        int img  = (idx >> 5) & 1;
        int kt2  = (idx >> 6) & 3;
        int nt   = (idx >> 8) & 3;
        int ng   = (idx >> 10) & 3;
        int chunk = isproj ? 0 : (idx >> 12);
        int n = ng * 32 + nt * 8 + (lane >> 2);
        uint32_t r[4];
        #pragma unroll
        for (int m = 0; m < 4; m++) {
            int k = kt2 * 32 + m * 8 + 2 * (lane & 3);
            float w0, w1;
            if (isproj) { w0 = proj_w[k * 128 + n];              w1 = proj_w[(k + 1) * 128 + n]; }
            else        { w0 = qkv_w[k * 384 + chunk * 128 + n]; w1 = qkv_w[(k + 1) * 384 + chunk * 128 + n]; }
            r[m] = pack_split(w0, w1, img);
        }
        uint4 v = make_uint4(r[0], r[1], r[2], r[3]);
        if (isproj) g_BprojF[idx] = v; else g_BqkvF[idx] = v;
    }
}

__global__ __launch_bounds__(NTHREADS, 2)
void swin_mma_kernel(const float* __restrict__ x_g,
                     const float* __restrict__ qkv_b,
                     const float* __restrict__ proj_b,
                     float* __restrict__ out_g) {
    const int blk  = blockIdx.x;
    const int wi   = blk & (NWIN - 1);
    const int tid  = threadIdx.x;
    const int lane = tid & 31;
    const int warp = tid >> 5;            // 0..7

    extern __shared__ float smem[];
    char* smb = reinterpret_cast<char*>(smem);
    const uint32_t smem_base = smem_u32(smem);

    const int mt  = warp & 3;
    const int ng2 = warp >> 2;
    const int mtb = (mt < 3) ? mt * 16 : 33;
    const int r1  = mtb + (lane >> 2);
    const int r2  = r1 + 8;

    // ---- phase 1a: WARP-LOCAL x -> A images for this warp's 16 rows;
    //      V pad rows zeroed block-wide (visibility covered by post-QKV barrier) ----
    {
        const float2* xin = reinterpret_cast<const float2*>(x_g + (size_t)blk * (NTOK * CDIM));
        for (int t = lane; t < 16 * 64; t += 32) {
            int row = mtb + (t >> 6);
            int kp  = t & 63;
            float2 v = xin[row * 64 + kp];
            uint32_t hp, lp; split2(v.x, v.y, hp, lp);
            uint32_t off = (uint32_t)row * 256 + (((kp >> 2) ^ (row & 7)) << 4) + (kp & 3) * 4;
            *reinterpret_cast<uint32_t*>(smb + RA_HI + off) = hp;
            *reinterpret_cast<uint32_t*>(smb + RA_LO + off) = lp;
        }
        for (int o = tid; o < 480; o += NTHREADS) {   // V rows 49..63, both imgs
            int img = o / 240, rem = o % 240;
            int r = 49 + rem / 16, c = rem % 16;
            *reinterpret_cast<float4*>(smb + RV_HI + img * 16384 + r * 256 + c * 16) =
                make_float4(0.f, 0.f, 0.f, 0.f);
        }
        __syncwarp();
    }

    // ---- QKV GEMM: order K, V, Q (Q result stays in registers); dual accumulators ----
    float vQ[8][4];
    {
        uint32_t aH[8][4], aL[8][4];
        const int arow = mtb + (lane & 15);
        #pragma unroll
        for (int k = 0; k < 8; k++) {
            uint32_t off = (uint32_t)arow * 256 + (((2 * k + (lane >> 4)) ^ (arow & 7)) << 4);
            ldmx4(aH[k], smem_base + RA_HI + off);
            ldmx4(aL[k], smem_base + RA_LO + off);
        }

        #pragma unroll
        for (int ckx = 0; ckx < 3; ckx++) {
            const int ck = (ckx == 0) ? 1 : (ckx == 1) ? 2 : 0;   // K, V, Q
            #pragma unroll
            for (int nt8 = 0; nt8 < 8; nt8++) {
                const int ng4 = ng2 * 2 + (nt8 >> 2);
                const int nt4 = nt8 & 3;
                const uint4* fb = g_BqkvF + (size_t)(((ck * 4 + ng4) * 4 + nt4) * 256) + lane;
                float cA[4] = {0.f, 0.f, 0.f, 0.f};
                float cB[4] = {0.f, 0.f, 0.f, 0.f};
                #pragma unroll
                for (int kt2 = 0; kt2 < 4; kt2++) {
                    float* c = (kt2 < 2) ? cA : cB;
                    uint4 bhv = __ldg(fb + kt2 * 64);
                    uint4 blv = __ldg(fb + kt2 * 64 + 32);
                    mma16816(c, aH[2 * kt2],     bhv.x, bhv.y);
                    mma16816(c, aH[2 * kt2],     blv.x, blv.y);
                    mma16816(c, aL[2 * kt2],     bhv.x, bhv.y);
                    mma16816(c, aH[2 * kt2 + 1], bhv.z, bhv.w);
                    mma16816(c, aH[2 * kt2 + 1], blv.z, blv.w);
                    mma16816(c, aL[2 * kt2 + 1], bhv.z, bhv.w);
                }
                const int n0 = ng2 * 64 + nt8 * 8;
                const int coll = n0 + 2 * (lane & 3);
                float2 bias = __ldg(reinterpret_cast<const float2*>(qkv_b + ck * 128 + coll));
                float v0 = cA[0] + cB[0] + bias.x, v1 = cA[1] + cB[1] + bias.y;
                float v2 = cA[2] + cB[2] + bias.x, v3 = cA[3] + cB[3] + bias.y;
                if (ck == 0) {
                    vQ[nt8][0] = v0; vQ[nt8][1] = v1; vQ[nt8][2] = v2; vQ[nt8][3] = v3;
                } else {
                    const int bh = (ck == 1) ? RK_HI : RV_HI;
                    const int bl = (ck == 1) ? RK_LO : RV_LO;
                    const int chnk = ng2 * 8 + nt8;
                    uint32_t hp, lp;
                    split2(v0, v1, hp, lp);
                    uint32_t o1 = (uint32_t)r1 * 256 + ((chnk ^ (r1 & 7)) << 4) + 4 * (lane & 3);
                    *reinterpret_cast<uint32_t*>(smb + bh + o1) = hp;
                    *reinterpret_cast<uint32_t*>(smb + bl + o1) = lp;
                    split2(v2, v3, hp, lp);
                    uint32_t o2 = (uint32_t)r2 * 256 + ((chnk ^ (r2 & 7)) << 4) + 4 * (lane & 3);
                    *reinterpret_cast<uint32_t*>(smb + bh + o2) = hp;
                    *reinterpret_cast<uint32_t*>(smb + bl + o2) = lp;
                }
            }
        }
    }
    __syncthreads();

    // ---- attention: unit u -> head h = 2*ng2+u, rows = this warp's mtb tile ----
    {
        const float scale = 0.17677669529663687f;   // 1/sqrt(32)
        #pragma unroll
        for (int u = 0; u < 2; u++) {
            const int h = 2 * ng2 + u;

            // pack Q A-fragments (hi/lo) straight from QKV C-frags
            uint32_t qH[2][4], qL[2][4];
            #pragma unroll
            for (int ks = 0; ks < 2; ks++) {
                const int t0 = 4 * u + 2 * ks, t1 = t0 + 1;
                split2(vQ[t0][0], vQ[t0][1], qH[ks][0], qL[ks][0]);
                split2(vQ[t0][2], vQ[t0][3], qH[ks][1], qL[ks][1]);
                split2(vQ[t1][0], vQ[t1][1], qH[ks][2], qL[ks][2]);
                split2(vQ[t1][2], vQ[t1][3], qH[ks][3], qL[ks][3]);
            }

            // prefetch comb rows
            const float* cb1 = g_comb2 + (((size_t)(wi * NHEADS + h) * NTOK) + r1) * 64 + 2 * (lane & 3);
            const float* cb2 = g_comb2 + (((size_t)(wi * NHEADS + h) * NTOK) + r2) * 64 + 2 * (lane & 3);
            float2 cv1[7], cv2[7];
            #pragma unroll
            for (int nt = 0; nt < 7; nt++) {
                cv1[nt] = __ldg(reinterpret_cast<const float2*>(cb1 + nt * 8));
                cv2[nt] = __ldg(reinterpret_cast<const float2*>(cb2 + nt * 8));
            }

            // S = Q K^T (dual accumulators: one per k-half)
            float cS[7][4];
            #pragma unroll
            for (int nt = 0; nt < 7; nt++) {
                const int krow = nt * 8 + (lane & 7);
                uint32_t koff = (uint32_t)krow * 256 + (((4 * h + ((lane >> 3) & 3)) ^ (krow & 7)) << 4);
                uint32_t bH[4], bL[4];
                ldmx4(bH, smem_base + RK_HI + koff);
                ldmx4(bL, smem_base + RK_LO + koff);
                float cA[4] = {0.f, 0.f, 0.f, 0.f};
                float cB[4] = {0.f, 0.f, 0.f, 0.f};
                mma16816(cA, qH[0], bH[0], bH[1]);
                mma16816(cA, qH[0], bL[0], bL[1]);
                mma16816(cA, qL[0], bH[0], bH[1]);
                mma16816(cB, qH[1], bH[2], bH[3]);
                mma16816(cB, qH[1], bL[2], bL[3]);
                mma16816(cB, qL[1], bH[2], bH[3]);
                cS[nt][0] = cA[0] + cB[0];
                cS[nt][1] = cA[1] + cB[1];
                cS[nt][2] = cA[2] + cB[2];
                cS[nt][3] = cA[3] + cB[3];
            }

            // softmax in registers (no max pass; logits tiny)
            float s0 = 0.f, s1 = 0.f;
            #pragma unroll
            for (int nt = 0; nt < 7; nt++) {
                float a0 = __expf(fmaf(cS[nt][0], scale, cv1[nt].x));
                float a1 = __expf(fmaf(cS[nt][1], scale, cv1[nt].y));
                float a2 = __expf(fmaf(cS[nt][2], scale, cv2[nt].x));
                float a3 = __expf(fmaf(cS[nt][3], scale, cv2[nt].y));
                if (nt == 6) {
                    bool v0 = ((lane & 3) == 0);    // only j=48 valid
                    a0 = v0 ? a0 : 0.f;  a1 = 0.f;
                    a2 = v0 ? a2 : 0.f;  a3 = 0.f;
                }
                cS[nt][0] = a0; cS[nt][1] = a1; cS[nt][2] = a2; cS[nt][3] = a3;
                s0 += a0 + a1;  s1 += a2 + a3;
            }
            s0 += __shfl_xor_sync(0xffffffffu, s0, 1);
            s0 += __shfl_xor_sync(0xffffffffu, s0, 2);
            s1 += __shfl_xor_sync(0xffffffffu, s1, 1);
            s1 += __shfl_xor_sync(0xffffffffu, s1, 2);
            float i0 = 1.0f / s0, i1 = 1.0f / s1;

            // pack P A-fragments (hi/lo)
            uint32_t paH[4][4], paL[4][4];
            #pragma unroll
            for (int m = 0; m < 4; m++) {
                split2(cS[2 * m][0] * i0, cS[2 * m][1] * i0, paH[m][0], paL[m][0]);
                split2(cS[2 * m][2] * i1, cS[2 * m][3] * i1, paH[m][1], paL[m][1]);
                if (2 * m + 1 < 7) {
                    split2(cS[2 * m + 1][0] * i0, cS[2 * m + 1][1] * i0, paH[m][2], paL[m][2]);
                    split2(cS[2 * m + 1][2] * i1, cS[2 * m + 1][3] * i1, paH[m][3], paL[m][3]);
                } else {
                    paH[m][2] = paL[m][2] = 0u;
                    paH[m][3] = paL[m][3] = 0u;
                }
            }

            // O = P @ V (trans loads); dual accumulators (j-blocks 0-1 vs 2-3)
            #pragma unroll
            for (int nt = 0; nt < 4; nt++) {
                const int cchunk = 4 * h + nt;
                const int ja = lane;            // j rows 0..31
                const int jb = lane + 32;       // j rows 32..63
                uint32_t voa = (uint32_t)ja * 256 + ((cchunk ^ (ja & 7)) << 4);
                uint32_t vob = (uint32_t)jb * 256 + ((cchunk ^ (jb & 7)) << 4);
                uint32_t vH0[4], vH1[4], vL0[4], vL1[4];
                ldmx4t(vH0, smem_base + RV_HI + voa);
                ldmx4t(vH1, smem_base + RV_HI + vob);
                ldmx4t(vL0, smem_base + RV_LO + voa);
                ldmx4t(vL1, smem_base + RV_LO + vob);

                float cA[4] = {0.f, 0.f, 0.f, 0.f};
                float cB[4] = {0.f, 0.f, 0.f, 0.f};
                mma16816(cA, paH[0], vH0[0], vH0[1]);
                mma16816(cA, paH[0], vL0[0], vL0[1]);
                mma16816(cA, paL[0], vH0[0], vH0[1]);
                mma16816(cA, paH[1], vH0[2], vH0[3]);
                mma16816(cA, paH[1], vL0[2], vL0[3]);
                mma16816(cA, paL[1], vH0[2], vH0[3]);
                mma16816(cB, paH[2], vH1[0], vH1[1]);
                mma16816(cB, paH[2], vL1[0], vL1[1]);
                mma16816(cB, paL[2], vH1[0], vH1[1]);
                mma16816(cB, paH[3], vH1[2], vH1[3]);
                mma16816(cB, paH[3], vL1[2], vL1[3]);
                mma16816(cB, paL[3], vH1[2], vH1[3]);

                uint32_t hp, lp;
                split2(cA[0] + cB[0], cA[1] + cB[1], hp, lp);
                uint32_t o1 = (uint32_t)r1 * 256 + ((cchunk ^ (r1 & 7)) << 4) + 4 * (lane & 3);
                *reinterpret_cast<uint32_t*>(smb + AP_HI + o1) = hp;
                *reinterpret_cast<uint32_t*>(smb + AP_LO + o1) = lp;
                split2(cA[2] + cB[2], cA[3] + cB[3], hp, lp);
                uint32_t o2 = (uint32_t)r2 * 256 + ((cchunk ^ (r2 & 7)) << 4) + 4 * (lane & 3);
                *reinterpret_cast<uint32_t*>(smb + AP_HI + o2) = hp;
                *reinterpret_cast<uint32_t*>(smb + AP_LO + o2) = lp;
            }
        }
    }
    __syncthreads();

    // ---- proj via mma, fragment-direct B; dual accumulators; output -> global ----
    {
        uint32_t oH[8][4], oL[8][4];
        const int arow = mtb + (lane & 15);
        #pragma unroll
        for (int k = 0; k < 8; k++) {
            uint32_t off = (uint32_t)arow * 256 + (((2 * k + (lane >> 4)) ^ (arow & 7)) << 4);
            ldmx4(oH[k], smem_base + AP_HI + off);
            ldmx4(oL[k], smem_base + AP_LO + off);
        }
        float* outp = out_g + (size_t)blk * (NTOK * CDIM);
        #pragma unroll
        for (int nt8 = 0; nt8 < 8; nt8++) {
            const int ng4 = ng2 * 2 + (nt8 >> 2);
            const int nt4 = nt8 & 3;
            const uint4* fb = g_BprojF + (size_t)((ng4 * 4 + nt4) * 256) + lane;
            float cA[4] = {0.f, 0.f, 0.f, 0.f};
            float cB[4] = {0.f, 0.f, 0.f, 0.f};
            #pragma unroll
            for (int kt2 = 0; kt2 < 4; kt2++) {
                float* c = (kt2 < 2) ? cA : cB;
                uint4 bhv = __ldg(fb + kt2 * 64);
                uint4 blv = __ldg(fb + kt2 * 64 + 32);
                mma16816(c, oH[2 * kt2],     bhv.x, bhv.y);
                mma16816(c, oH[2 * kt2],     blv.x, blv.y);
                mma16816(c, oL[2 * kt2],     bhv.x, bhv.y);
                mma16816(c, oH[2 * kt2 + 1], bhv.z, bhv.w);
                mma16816(c, oH[2 * kt2 + 1], blv.z, blv.w);
                mma16816(c, oL[2 * kt2 + 1], bhv.z, bhv.w);
            }
            const int n0 = ng2 * 64 + nt8 * 8;
            const int coll = n0 + 2 * (lane & 3);
            float2 bias = __ldg(reinterpret_cast<const float2*>(proj_b + coll));
            *reinterpret_cast<float2*>(outp + r1 * CDIM + coll) =
                make_float2(cA[0] + cB[0] + bias.x, cA[1] + cB[1] + bias.y);
            *reinterpret_cast<float2*>(outp + r2 * CDIM + coll) =
                make_float2(cA[2] + cB[2] + bias.x, cA[3] + cB[3] + bias.y);
        }
    }
}

extern "C" void kernel_launch(void* const* d_in, const int* in_sizes, int n_in,
                              void* d_out, int out_size) {
    const float* x      = (const float*)d_in[0];
    const float* mask   = (const float*)d_in[1];
    const float* qkv_w  = (const float*)d_in[2];
    const float* qkv_b  = (const float*)d_in[3];
    const float* proj_w = (const float*)d_in[4];
    const float* proj_b = (const float*)d_in[5];
    const float* rel    = (const float*)d_in[6];
    float* out = (float*)d_out;

    (void)in_sizes; (void)n_in; (void)out_size;

    cudaFuncSetAttribute(swin_mma_kernel,
                         cudaFuncAttributeMaxDynamicSharedMemorySize, SMEM_TOTAL_B);

    swin_prol_kernel<<<COMB_BLKS + 64, 256>>>(rel, mask, qkv_w, proj_w);
    swin_mma_kernel<<<NBLK, NTHREADS, SMEM_TOTAL_B>>>(x, qkv_b, proj_b, out);
}